// round 1
// baseline (speedup 1.0000x reference)
#include <cuda_runtime.h>

// Subtraction2: out[n,c,p,y*112+x] = in1[n,c,y,x] - in2_padded[n,c,y+di-3,x+dj-3]
// p = di*7+dj, 7x7 kernel, stride 1, dilation 1, pad 3. H=W=112, N=8, C=32.
// Output: 8*32*49*12544 fp32 = 629 MB -> pure HBM-write-bound kernel.

#define H 112
#define W 112
#define HW (H * W)          // 12544
#define KK 49
#define TY 8                // output rows per block
#define TPB 224             // 28 x-quads * 8 rows
#define SROW 120            // smem row: cols -4..115 (16B-aligned windows)

__global__ __launch_bounds__(TPB)
void sub2_kernel(const float* __restrict__ in1,
                 const float* __restrict__ in2,
                 float* __restrict__ out) {
    __shared__ float s[TY + 6][SROW];

    const int tile  = blockIdx.x;            // 0..13  (y tile)
    const int plane = blockIdx.y;            // 0..255 (n*c)
    const int y0    = tile * TY;
    const int tid   = threadIdx.x;

    // ---- fill input2 tile (rows y0-3 .. y0+TY+2, cols -4..115, zero halo) ----
    const float* p2 = in2 + (size_t)plane * HW;
    #pragma unroll
    for (int i = tid; i < (TY + 6) * SROW; i += TPB) {
        const int r  = i / SROW;
        const int ci = i - r * SROW;
        const int gr = y0 - 3 + r;           // global row
        const int gc = ci - 4;               // global col
        float v = 0.0f;
        if ((unsigned)gr < (unsigned)H && (unsigned)gc < (unsigned)W)
            v = p2[gr * W + gc];
        s[r][ci] = v;
    }
    __syncthreads();

    const int tx = tid % 28;                 // x-quad index
    const int ty = tid / 28;                 // row within tile
    const int x  = tx * 4;
    const int y  = y0 + ty;

    const float4 c = *reinterpret_cast<const float4*>(
        in1 + (size_t)plane * HW + y * W + x);

    float* obase = out + (size_t)plane * KK * HW + y * W + x;

    #pragma unroll
    for (int di = 0; di < 7; di++) {
        // Aligned 12-float register window: global cols x-4 .. x+7
        // (smem col index of global col g is g+4, so window starts at s[..][x])
        const float4 w0 = *reinterpret_cast<const float4*>(&s[ty + di][x]);
        const float4 w1 = *reinterpret_cast<const float4*>(&s[ty + di][x + 4]);
        const float4 w2 = *reinterpret_cast<const float4*>(&s[ty + di][x + 8]);
        float w[12];
        w[0] = w0.x; w[1]  = w0.y; w[2]  = w0.z; w[3]  = w0.w;
        w[4] = w1.x; w[5]  = w1.y; w[6]  = w1.z; w[7]  = w1.w;
        w[8] = w2.x; w[9]  = w2.y; w[10] = w2.z; w[11] = w2.w;

        #pragma unroll
        for (int dj = 0; dj < 7; dj++) {
            // neighbor col for out element e is x+e+dj-3 -> window index dj+1+e
            float4 o;
            o.x = c.x - w[dj + 1];
            o.y = c.y - w[dj + 2];
            o.z = c.z - w[dj + 3];
            o.w = c.w - w[dj + 4];
            __stcs(reinterpret_cast<float4*>(obase + (size_t)(di * 7 + dj) * HW), o);
        }
    }
}

extern "C" void kernel_launch(void* const* d_in, const int* in_sizes, int n_in,
                              void* d_out, int out_size) {
    const float* in1 = (const float*)d_in[0];
    const float* in2 = (const float*)d_in[1];
    float* out = (float*)d_out;

    dim3 grid(H / TY, 8 * 32);   // 14 y-tiles x 256 planes
    sub2_kernel<<<grid, TPB>>>(in1, in2, out);
}